// round 8
// baseline (speedup 1.0000x reference)
#include <cuda_runtime.h>
#include <math_constants.h>

#define IMG_H 1024
#define IMG_W 1024
#define IMG   (IMG_H * IMG_W)
#define NIMG  16
#define NF    32            // [0..15]=pred(sigmoid(logits)), [16..31]=gt(target)
#define OUTC  248           // output cols per warp (256-col window, 4-col halo/side)
#define XT    5             // ceil(1024/248)
#define R     32            // output rows per warp
#define NWARP 4
#define FINF  CUDART_INF_F

__device__ float  g_bufA[(size_t)NF * IMG];   // 128 MB scratch
__device__ float  g_bufB[(size_t)NF * IMG];   // 128 MB scratch
__device__ double g_acc[NF];                  // [0..15]=tp, [16..31]=ts

struct f8 { float4 l, h; };

__device__ __forceinline__ float sigmoidf(float x) { return 1.f / (1.f + __expf(-x)); }
__device__ __forceinline__ float4 s4(float4 v) {
    return make_float4(sigmoidf(v.x), sigmoidf(v.y), sigmoidf(v.z), sigmoidf(v.w));
}
__device__ __forceinline__ float4 i2f4(int4 t) {
    return make_float4((float)t.x, (float)t.y, (float)t.z, (float)t.w);
}
__device__ __forceinline__ float4 vmin3(float4 a, float4 b, float4 c) {
    return make_float4(fminf(a.x, fminf(b.x, c.x)), fminf(a.y, fminf(b.y, c.y)),
                       fminf(a.z, fminf(b.z, c.z)), fminf(a.w, fminf(b.w, c.w)));
}
__device__ __forceinline__ float4 vmax3(float4 a, float4 b, float4 c) {
    return make_float4(fmaxf(a.x, fmaxf(b.x, c.x)), fmaxf(a.y, fmaxf(b.y, c.y)),
                       fmaxf(a.z, fmaxf(b.z, c.z)), fmaxf(a.w, fmaxf(b.w, c.w)));
}
__device__ __forceinline__ f8 vmin38(f8 a, f8 b, f8 c) {
    f8 r; r.l = vmin3(a.l, b.l, c.l); r.h = vmin3(a.h, b.h, c.h); return r;
}
__device__ __forceinline__ f8 vmax38(f8 a, f8 b, f8 c) {
    f8 r; r.l = vmax3(a.l, b.l, c.l); r.h = vmax3(a.h, b.h, c.h); return r;
}
__device__ __forceinline__ f8 vmin28(f8 a, f8 m) {
    f8 r;
    r.l = make_float4(fminf(a.l.x, m.l.x), fminf(a.l.y, m.l.y),
                      fminf(a.l.z, m.l.z), fminf(a.l.w, m.l.w));
    r.h = make_float4(fminf(a.h.x, m.h.x), fminf(a.h.y, m.h.y),
                      fminf(a.h.z, m.h.z), fminf(a.h.w, m.h.w));
    return r;
}
__device__ __forceinline__ f8 vmax28(f8 a, f8 m) {
    f8 r;
    r.l = make_float4(fmaxf(a.l.x, m.l.x), fmaxf(a.l.y, m.l.y),
                      fmaxf(a.l.z, m.l.z), fmaxf(a.l.w, m.l.w));
    r.h = make_float4(fmaxf(a.h.x, m.h.x), fmaxf(a.h.y, m.h.y),
                      fmaxf(a.h.z, m.h.z), fmaxf(a.h.w, m.h.w));
    return r;
}
__device__ __forceinline__ f8 hmin8(f8 v) {
    float l = __shfl_up_sync(0xffffffffu, v.h.w, 1);
    float r = __shfl_down_sync(0xffffffffu, v.l.x, 1);
    f8 o;
    o.l.x = fminf(l,     fminf(v.l.x, v.l.y));
    o.l.y = fminf(v.l.x, fminf(v.l.y, v.l.z));
    o.l.z = fminf(v.l.y, fminf(v.l.z, v.l.w));
    o.l.w = fminf(v.l.z, fminf(v.l.w, v.h.x));
    o.h.x = fminf(v.l.w, fminf(v.h.x, v.h.y));
    o.h.y = fminf(v.h.x, fminf(v.h.y, v.h.z));
    o.h.z = fminf(v.h.y, fminf(v.h.z, v.h.w));
    o.h.w = fminf(v.h.z, fminf(v.h.w, r));
    return o;
}
__device__ __forceinline__ f8 hmax8(f8 v) {
    float l = __shfl_up_sync(0xffffffffu, v.h.w, 1);
    float r = __shfl_down_sync(0xffffffffu, v.l.x, 1);
    f8 o;
    o.l.x = fmaxf(l,     fmaxf(v.l.x, v.l.y));
    o.l.y = fmaxf(v.l.x, fmaxf(v.l.y, v.l.z));
    o.l.z = fmaxf(v.l.y, fmaxf(v.l.z, v.l.w));
    o.l.w = fmaxf(v.l.z, fmaxf(v.l.w, v.h.x));
    o.h.x = fmaxf(v.l.w, fmaxf(v.h.x, v.h.y));
    o.h.y = fmaxf(v.h.x, fmaxf(v.h.y, v.h.z));
    o.h.z = fmaxf(v.h.y, fmaxf(v.h.z, v.h.w));
    o.h.w = fmaxf(v.h.z, fmaxf(v.h.w, r));
    return o;
}
__device__ __forceinline__ float4 upd4(float4 x, float4 op, float4 er) {
    return make_float4(__saturatef(x.x - (op.x - er.x)),
                       __saturatef(x.y - (op.y - er.y)),
                       __saturatef(x.z - (op.z - er.z)),
                       __saturatef(x.w - (op.w - er.w)));
}
__device__ __forceinline__ f8 upd8(f8 x, f8 op, f8 er) {
    f8 r; r.l = upd4(x.l, op.l, er.l); r.h = upd4(x.h, op.h, er.h); return r;
}

// ---------------------------------------------------------------------------
// MODE 0: x = sigmoid(logits)/(float)target; 2 skeleton iterations; store.
// MODE 1: load buffer; 2 skeleton iterations; store.
// MODE 2: load buffer; 1 skeleton iteration; accumulate tp/ts (no store).
// Each lane owns 8 columns (2x float4); 2 shuffles per stencil stage per row.
// ---------------------------------------------------------------------------
template<int MODE>
__global__ void __launch_bounds__(NWARP * 32)
skel_kernel(const float* __restrict__ src,
            const float* __restrict__ logits,
            const int*   __restrict__ target,
            float*       __restrict__ dst)
{
    const int lane = threadIdx.x & 31;
    const int warp = threadIdx.x >> 5;
    const int z    = blockIdx.z;
    const int c0   = blockIdx.x * OUTC - 4 + lane * 8;   // lane cols c0..c0+7
    const int row0 = (blockIdx.y * NWARP + warp) * R;

    bool vv[8];
    #pragma unroll
    for (int i = 0; i < 8; ++i) vv[i] = (unsigned)(c0 + i) < IMG_W;
    const bool allL = vv[0] && vv[3];   // c0>=0 always when emitted; left tile c0=-4 lane0 only
    const bool allLo = (c0 >= 0) && vv[3];
    const bool allHi = vv[4 + 3] && ((c0 + 4) >= 0);
    // mask vectors: fmin with mN -> invalid col -inf; fmax with mP -> +inf
    f8 mN, mP;
    {
        float* n = (float*)&mN; float* p = (float*)&mP;
        #pragma unroll
        for (int i = 0; i < 8; ++i) {
            n[i] = vv[i] ?  FINF : -FINF;
            p[i] = vv[i] ? -FINF :  FINF;
        }
    }

    if (MODE == 0 && blockIdx.x == 0 && blockIdx.y == 0 && blockIdx.z == 0 &&
        threadIdx.x < NF)
        g_acc[threadIdx.x] = 0.0;   // stream-ordered before MODE 2 atomics

    const int img = (z < NIMG) ? z : z - NIMG;
    const float* __restrict__ lg = logits + (size_t)img * IMG;
    const int*   __restrict__ tg = target + (size_t)img * IMG;
    const float* __restrict__ sp = (MODE != 0) ? src + (size_t)z * IMG : nullptr;
    float* __restrict__ dp = (MODE != 2) ? dst + (size_t)z * IMG : nullptr;

    const float4 P44 = make_float4(FINF, FINF, FINF, FINF);
    f8 P8; P8.l = P44; P8.h = P44;
    f8 N8; N8.l = make_float4(-FINF, -FINF, -FINF, -FINF); N8.h = N8.l;

    auto ld4 = [&](long long rb, int cb, bool allc) -> float4 {
        if (allc) {
            if (MODE == 0) {
                if (z < NIMG) return s4(__ldg((const float4*)(lg + rb + cb)));
                return i2f4(__ldg((const int4*)(tg + rb + cb)));
            }
            return __ldg((const float4*)(sp + rb + cb));
        }
        float4 r = P44;
        float* rr = (float*)&r;
        #pragma unroll
        for (int i = 0; i < 4; ++i) {
            long long idx = rb + cb + i;
            if ((unsigned)(cb + i) < IMG_W) {
                if (MODE == 0)
                    rr[i] = (z < NIMG) ? sigmoidf(__ldg(lg + idx))
                                       : (float)__ldg(tg + idx);
                else
                    rr[i] = __ldg(sp + idx);
            }
        }
        return r;
    };
    auto ldrow = [&](int r) -> f8 {
        if ((unsigned)r >= IMG_H) return P8;
        long long rb = (long long)r * IMG_W;
        f8 o;
        o.l = ld4(rb, c0, allLo);
        o.h = ld4(rb, c0 + 4, allHi);
        return o;
    };

    const bool emitL = (lane != 0);    // L half = cols c0..c0+3 (halo for lane 0)
    const bool emitH = (lane != 31);   // H half (halo for lane 31)
    float accum = 0.f;

    auto storeHalf = [&](long long rowbase, int cb, float4 v, bool emit, bool allc) {
        if (!emit) return;
        if (allc) { *(float4*)(dp + rowbase + cb) = v; return; }
        const float* vp = (const float*)&v;
        #pragma unroll
        for (int i = 0; i < 4; ++i)
            if ((unsigned)(cb + i) < IMG_W) dp[rowbase + cb + i] = vp[i];
    };
    auto weightHalf = [&](long long rowbase, int cb, bool allc) -> float4 {
        if (allc) {
            if (z < NIMG) return i2f4(__ldg((const int4*)(tg + rowbase + cb)));
            return s4(__ldg((const float4*)(lg + rowbase + cb)));
        }
        float4 w = make_float4(0.f, 0.f, 0.f, 0.f);
        float* wp = (float*)&w;
        #pragma unroll
        for (int i = 0; i < 4; ++i)
            if ((unsigned)(cb + i) < IMG_W)
                wp[i] = (z < NIMG) ? (float)__ldg(tg + rowbase + cb + i)
                                   : sigmoidf(__ldg(lg + rowbase + cb + i));
        return w;
    };

    if (MODE != 2) {
        // ---- two fused skeleton iterations (lag-4 rolling pipeline) ----
        f8 xa = ldrow(row0 - 4), xb = ldrow(row0 - 3);
        f8 e1a = N8, e1b = N8, pa = P8, pb = P8, qa = N8, qb = N8;
        #pragma unroll 2
        for (int k = row0 - 3; k <= row0 + R + 2; ++k) {
            f8 xc = ldrow(k + 1);
            f8 e1 = ((unsigned)k < IMG_H)
                  ? vmin28(hmin8(vmin38(xa, xb, xc)), mN) : N8;
            f8 op1 = hmax8(vmax38(e1a, e1b, e1));
            f8 xp  = ((unsigned)(k - 1) < IMG_H)
                   ? vmax28(upd8(xa, op1, e1b), mP) : P8;
            f8 e2 = ((unsigned)(k - 2) < IMG_H)
                  ? vmin28(hmin8(vmin38(pa, pb, xp)), mN) : N8;
            if (k >= row0 + 3) {
                f8 op2 = hmax8(vmax38(qa, qb, e2));
                f8 nx  = upd8(pa, op2, qb);
                long long ob = (long long)(k - 3) * IMG_W;
                storeHalf(ob, c0,     nx.l, emitL, allLo);
                storeHalf(ob, c0 + 4, nx.h, emitH, allHi);
            }
            qa = qb; qb = e2; pa = pb; pb = xp;
            e1a = e1b; e1b = e1; xa = xb; xb = xc;
        }
    } else {
        // ---- final skeleton iteration + reduction ----
        f8 xa = ldrow(row0 - 2), xb = ldrow(row0 - 1);
        f8 e1a = N8, e1b = N8;
        #pragma unroll 2
        for (int k = row0 - 1; k <= row0 + R; ++k) {
            f8 xc = ldrow(k + 1);
            f8 e1 = ((unsigned)k < IMG_H)
                  ? vmin28(hmin8(vmin38(xa, xb, xc)), mN) : N8;
            if (k >= row0 + 1) {
                f8 op = hmax8(vmax38(e1a, e1b, e1));
                f8 nx = upd8(xa, op, e1b);             // row k-1, saturated
                long long ob = (long long)(k - 1) * IMG_W;
                if (emitL) {
                    float4 w = weightHalf(ob, c0, allLo);
                    accum += nx.l.x * w.x + nx.l.y * w.y + nx.l.z * w.z + nx.l.w * w.w;
                }
                if (emitH) {
                    float4 w = weightHalf(ob, c0 + 4, allHi);
                    accum += nx.h.x * w.x + nx.h.y * w.y + nx.h.z * w.z + nx.h.w * w.w;
                }
            }
            e1a = e1b; e1b = e1; xa = xb; xb = xc;
        }
        #pragma unroll
        for (int o = 16; o > 0; o >>= 1)
            accum += __shfl_down_sync(0xffffffffu, accum, o);
        __shared__ float sacc[NWARP];
        if (lane == 0) sacc[warp] = accum;
        __syncthreads();
        if (threadIdx.x == 0) {
            float t = 0.f;
            #pragma unroll
            for (int i = 0; i < NWARP; ++i) t += sacc[i];
            atomicAdd(&g_acc[z], (double)t);
        }
    }
}

// ---------------------------------------------------------------------------
__global__ void final_kernel(float* __restrict__ out)
{
    const int t = threadIdx.x;
    float v = 0.f;
    if (t < NIMG) {
        double tp = g_acc[t], ts = g_acc[NIMG + t];
        double num = 2.0 * tp * ts;
        double den = tp + ts;
        double c = (den > 0.0) ? (num + 1e-6) / (den + 1e-6) : 1.0;
        c = fmin(fmax(c, 0.0), 1.0);
        v = (float)(1.0 - c);
    }
    for (int o = 16; o > 0; o >>= 1) v += __shfl_down_sync(0xffffffffu, v, o);
    if (t == 0) out[0] = v / (float)NIMG;
}

// ---------------------------------------------------------------------------
extern "C" void kernel_launch(void* const* d_in, const int* in_sizes, int n_in,
                              void* d_out, int out_size)
{
    const float* logits = (const float*)d_in[0];
    const int*   target = (const int*)d_in[1];
    float*       out    = (float*)d_out;

    float *A = nullptr, *B = nullptr;
    cudaGetSymbolAddress((void**)&A, g_bufA);
    cudaGetSymbolAddress((void**)&B, g_bufB);

    dim3 grid(XT, IMG_H / (R * NWARP), NF);   // 5 x 8 x 32 = 1280 blocks
    const int blk = NWARP * 32;

    skel_kernel<0><<<grid, blk>>>(nullptr, logits, target, A);  // sigmoid + iters 1-2
    skel_kernel<1><<<grid, blk>>>(A, nullptr, nullptr, B);      // iters 3-4
    skel_kernel<2><<<grid, blk>>>(B, logits, target, nullptr);  // iter 5 + reduce
    final_kernel<<<1, 32>>>(out);
}

// round 9
// speedup vs baseline: 1.3853x; 1.3853x over previous
#include <cuda_runtime.h>
#include <math_constants.h>

#define IMG_H 1024
#define IMG_W 1024
#define IMG   (IMG_H * IMG_W)
#define NIMG  16
#define NF    32            // [0..15]=pred(sigmoid(logits)), [16..31]=gt(target)
#define OUTC  120           // output cols per warp (128-col window, 4-col halo/side)
#define XT    9             // ceil(1024/120)
#define R     32            // output rows per warp
#define NWARP 4
#define FINF  CUDART_INF_F

__device__ float  g_bufA[(size_t)NF * IMG];   // 128 MB scratch
__device__ float  g_bufB[(size_t)NF * IMG];   // 128 MB scratch
__device__ double g_acc[NF];                  // [0..15]=tp, [16..31]=ts

__device__ __forceinline__ float sigmoidf(float x) { return 1.f / (1.f + __expf(-x)); }
__device__ __forceinline__ float4 s4(float4 v) {
    return make_float4(sigmoidf(v.x), sigmoidf(v.y), sigmoidf(v.z), sigmoidf(v.w));
}
__device__ __forceinline__ float4 i2f4(int4 t) {
    return make_float4((float)t.x, (float)t.y, (float)t.z, (float)t.w);
}
__device__ __forceinline__ float4 vmin3(float4 a, float4 b, float4 c) {
    return make_float4(fminf(a.x, fminf(b.x, c.x)), fminf(a.y, fminf(b.y, c.y)),
                       fminf(a.z, fminf(b.z, c.z)), fminf(a.w, fminf(b.w, c.w)));
}
__device__ __forceinline__ float4 vmax3(float4 a, float4 b, float4 c) {
    return make_float4(fmaxf(a.x, fmaxf(b.x, c.x)), fmaxf(a.y, fmaxf(b.y, c.y)),
                       fmaxf(a.z, fmaxf(b.z, c.z)), fmaxf(a.w, fmaxf(b.w, c.w)));
}
__device__ __forceinline__ float4 vmin2(float4 a, float4 m) {
    return make_float4(fminf(a.x, m.x), fminf(a.y, m.y),
                       fminf(a.z, m.z), fminf(a.w, m.w));
}
__device__ __forceinline__ float4 vmax2(float4 a, float4 m) {
    return make_float4(fmaxf(a.x, m.x), fmaxf(a.y, m.y),
                       fmaxf(a.z, m.z), fmaxf(a.w, m.w));
}
__device__ __forceinline__ float4 hmin(float4 v) {
    float l = __shfl_up_sync(0xffffffffu, v.w, 1);
    float r = __shfl_down_sync(0xffffffffu, v.x, 1);
    return make_float4(fminf(l,   fminf(v.x, v.y)),
                       fminf(v.x, fminf(v.y, v.z)),
                       fminf(v.y, fminf(v.z, v.w)),
                       fminf(v.z, fminf(v.w, r)));
}
__device__ __forceinline__ float4 hmax(float4 v) {
    float l = __shfl_up_sync(0xffffffffu, v.w, 1);
    float r = __shfl_down_sync(0xffffffffu, v.x, 1);
    return make_float4(fmaxf(l,   fmaxf(v.x, v.y)),
                       fmaxf(v.x, fmaxf(v.y, v.z)),
                       fmaxf(v.y, fmaxf(v.z, v.w)),
                       fmaxf(v.z, fmaxf(v.w, r)));
}
__device__ __forceinline__ float4 upd(float4 x, float4 op, float4 er) {
    return make_float4(__saturatef(x.x - (op.x - er.x)),
                       __saturatef(x.y - (op.y - er.y)),
                       __saturatef(x.z - (op.z - er.z)),
                       __saturatef(x.w - (op.w - er.w)));
}

// ---------------------------------------------------------------------------
// MODE 0: x = sigmoid(logits)/(float)target; 2 skeleton iterations; store.
// MODE 1: load buffer; 2 skeleton iterations; store.
// MODE 2: load buffer; 1 skeleton iteration; accumulate tp/ts (no store).
// Interior warps (73%) take a checkless fast path; edge warps take the
// fully-masked path (verbatim from the verified R5 kernel).
// ---------------------------------------------------------------------------
template<int MODE>
__global__ void __launch_bounds__(NWARP * 32)
skel_kernel(const float* __restrict__ src,
            const float* __restrict__ logits,
            const int*   __restrict__ target,
            float*       __restrict__ dst)
{
    const int lane = threadIdx.x & 31;
    const int warp = threadIdx.x >> 5;
    const int z    = blockIdx.z;
    const int c0   = blockIdx.x * OUTC - 4 + lane * 4;
    const int row0 = (blockIdx.y * NWARP + warp) * R;
    const bool v0 = (unsigned)c0       < IMG_W;
    const bool v1 = (unsigned)(c0 + 1) < IMG_W;
    const bool v2 = (unsigned)(c0 + 2) < IMG_W;
    const bool v3 = (unsigned)(c0 + 3) < IMG_W;
    const bool allv = (c0 >= 0) && (c0 + 3 < IMG_W);

    if (MODE == 0 && blockIdx.x == 0 && blockIdx.y == 0 && blockIdx.z == 0 &&
        threadIdx.x < NF)
        g_acc[threadIdx.x] = 0.0;   // stream-ordered before MODE 2 atomics

    const int img = (z < NIMG) ? z : z - NIMG;
    const float* __restrict__ lg = logits + (size_t)img * IMG;
    const int*   __restrict__ tg = target + (size_t)img * IMG;
    const float* __restrict__ sp = (MODE != 0) ? src + (size_t)z * IMG : nullptr;
    float* __restrict__ dp = (MODE != 2) ? dst + (size_t)z * IMG : nullptr;

    const float4 P4 = make_float4( FINF,  FINF,  FINF,  FINF);
    const float4 N4 = make_float4(-FINF, -FINF, -FINF, -FINF);
    const bool emitLane = (lane >= 1) && (lane <= 30);

    const bool cint = (blockIdx.x > 0) && (blockIdx.x < gridDim.x - 1);
    const bool rint = (row0 >= 4) && (row0 + R + 4 <= IMG_H);

    float accum = 0.f;

    if (cint && rint) {
        // =========== FAST PATH: no row/column checks, plain vector I/O =====
        auto ldF = [&](int r) -> float4 {
            size_t off = (size_t)r * IMG_W + c0;
            if (MODE == 0) {
                if (z < NIMG) return s4(__ldg((const float4*)(lg + off)));
                return i2f4(__ldg((const int4*)(tg + off)));
            }
            return __ldg((const float4*)(sp + off));
        };
        if (MODE != 2) {
            float4 xa = ldF(row0 - 4), xb = ldF(row0 - 3);
            float4 e1a = N4, e1b = N4, pa = P4, pb = P4, qa = N4, qb = N4;
            #pragma unroll 2
            for (int k = row0 - 3; k <= row0 + R + 2; ++k) {
                float4 xc  = ldF(k + 1);
                float4 e1  = hmin(vmin3(xa, xb, xc));
                float4 op1 = hmax(vmax3(e1a, e1b, e1));
                float4 xp  = upd(xa, op1, e1b);
                float4 e2  = hmin(vmin3(pa, pb, xp));
                if (k >= row0 + 3) {
                    float4 op2 = hmax(vmax3(qa, qb, e2));
                    float4 nx  = upd(pa, op2, qb);
                    if (emitLane)
                        *(float4*)(dp + (size_t)(k - 3) * IMG_W + c0) = nx;
                }
                qa = qb; qb = e2; pa = pb; pb = xp;
                e1a = e1b; e1b = e1; xa = xb; xb = xc;
            }
        } else {
            float4 xa = ldF(row0 - 2), xb = ldF(row0 - 1);
            float4 e1a = N4, e1b = N4;
            #pragma unroll 2
            for (int k = row0 - 1; k <= row0 + R; ++k) {
                float4 xc = ldF(k + 1);
                float4 e1 = hmin(vmin3(xa, xb, xc));
                if (k >= row0 + 1) {
                    float4 op = hmax(vmax3(e1a, e1b, e1));
                    float4 nx = upd(xa, op, e1b);
                    if (emitLane) {
                        size_t ob = (size_t)(k - 1) * IMG_W + c0;
                        float4 w = (z < NIMG) ? i2f4(__ldg((const int4*)(tg + ob)))
                                              : s4(__ldg((const float4*)(lg + ob)));
                        accum += nx.x * w.x + nx.y * w.y + nx.z * w.z + nx.w * w.w;
                    }
                }
                e1a = e1b; e1b = e1; xa = xb; xb = xc;
            }
        }
    } else {
        // =========== CHECKED PATH (verbatim logic from R5 champion) ========
        const float4 mN = make_float4(v0 ?  FINF : -FINF, v1 ?  FINF : -FINF,
                                      v2 ?  FINF : -FINF, v3 ?  FINF : -FINF);
        const float4 mP = make_float4(v0 ? -FINF :  FINF, v1 ? -FINF :  FINF,
                                      v2 ? -FINF :  FINF, v3 ? -FINF :  FINF);
        auto ld1 = [&](long long idx, bool v) -> float {
            if (!v) return FINF;
            if (MODE == 0)
                return (z < NIMG) ? sigmoidf(__ldg(lg + idx)) : (float)__ldg(tg + idx);
            return __ldg(sp + idx);
        };
        auto ldrow = [&](int r) -> float4 {
            if ((unsigned)r >= IMG_H) return P4;
            long long rb = (long long)r * IMG_W;
            if (allv) {
                if (MODE == 0) {
                    if (z < NIMG) return s4(__ldg((const float4*)(lg + rb + c0)));
                    return i2f4(__ldg((const int4*)(tg + rb + c0)));
                }
                return __ldg((const float4*)(sp + rb + c0));
            }
            return make_float4(ld1(rb + c0, v0), ld1(rb + c0 + 1, v1),
                               ld1(rb + c0 + 2, v2), ld1(rb + c0 + 3, v3));
        };

        if (MODE != 2) {
            float4 xa = ldrow(row0 - 4), xb = ldrow(row0 - 3);
            float4 e1a = N4, e1b = N4, pa = P4, pb = P4, qa = N4, qb = N4;
            for (int k = row0 - 3; k <= row0 + R + 2; ++k) {
                float4 xc = ldrow(k + 1);
                float4 e1 = ((unsigned)k < IMG_H)
                          ? vmin2(hmin(vmin3(xa, xb, xc)), mN) : N4;
                float4 op1 = hmax(vmax3(e1a, e1b, e1));
                float4 xp  = ((unsigned)(k - 1) < IMG_H)
                           ? vmax2(upd(xa, op1, e1b), mP) : P4;
                float4 e2 = ((unsigned)(k - 2) < IMG_H)
                          ? vmin2(hmin(vmin3(pa, pb, xp)), mN) : N4;
                if (k >= row0 + 3) {
                    float4 op2 = hmax(vmax3(qa, qb, e2));
                    float4 nx  = upd(pa, op2, qb);
                    if (emitLane) {
                        long long ob = (long long)(k - 3) * IMG_W + c0;
                        if (allv) {
                            *(float4*)(dp + ob) = nx;
                        } else {
                            if (v0) dp[ob]     = nx.x;
                            if (v1) dp[ob + 1] = nx.y;
                            if (v2) dp[ob + 2] = nx.z;
                            if (v3) dp[ob + 3] = nx.w;
                        }
                    }
                }
                qa = qb; qb = e2; pa = pb; pb = xp;
                e1a = e1b; e1b = e1; xa = xb; xb = xc;
            }
        } else {
            float4 xa = ldrow(row0 - 2), xb = ldrow(row0 - 1);
            float4 e1a = N4, e1b = N4;
            for (int k = row0 - 1; k <= row0 + R; ++k) {
                float4 xc = ldrow(k + 1);
                float4 e1 = ((unsigned)k < IMG_H)
                          ? vmin2(hmin(vmin3(xa, xb, xc)), mN) : N4;
                if (k >= row0 + 1) {
                    float4 op = hmax(vmax3(e1a, e1b, e1));
                    float4 nx = upd(xa, op, e1b);
                    if (emitLane) {
                        long long ob = (long long)(k - 1) * IMG_W + c0;
                        float4 w = make_float4(0.f, 0.f, 0.f, 0.f);
                        if (z < NIMG) {
                            if (allv) {
                                w = i2f4(__ldg((const int4*)(tg + ob)));
                            } else {
                                if (v0) w.x = (float)__ldg(tg + ob);
                                if (v1) w.y = (float)__ldg(tg + ob + 1);
                                if (v2) w.z = (float)__ldg(tg + ob + 2);
                                if (v3) w.w = (float)__ldg(tg + ob + 3);
                            }
                        } else {
                            if (allv) {
                                w = s4(__ldg((const float4*)(lg + ob)));
                            } else {
                                if (v0) w.x = sigmoidf(__ldg(lg + ob));
                                if (v1) w.y = sigmoidf(__ldg(lg + ob + 1));
                                if (v2) w.z = sigmoidf(__ldg(lg + ob + 2));
                                if (v3) w.w = sigmoidf(__ldg(lg + ob + 3));
                            }
                        }
                        accum += nx.x * w.x + nx.y * w.y + nx.z * w.z + nx.w * w.w;
                    }
                }
                e1a = e1b; e1b = e1; xa = xb; xb = xc;
            }
        }
    }

    if (MODE == 2) {
        #pragma unroll
        for (int o = 16; o > 0; o >>= 1)
            accum += __shfl_down_sync(0xffffffffu, accum, o);
        __shared__ float sacc[NWARP];
        if (lane == 0) sacc[warp] = accum;
        __syncthreads();
        if (threadIdx.x == 0) {
            float t = 0.f;
            #pragma unroll
            for (int i = 0; i < NWARP; ++i) t += sacc[i];
            atomicAdd(&g_acc[z], (double)t);
        }
    }
}

// ---------------------------------------------------------------------------
__global__ void final_kernel(float* __restrict__ out)
{
    const int t = threadIdx.x;
    float v = 0.f;
    if (t < NIMG) {
        double tp = g_acc[t], ts = g_acc[NIMG + t];
        double num = 2.0 * tp * ts;
        double den = tp + ts;
        double c = (den > 0.0) ? (num + 1e-6) / (den + 1e-6) : 1.0;
        c = fmin(fmax(c, 0.0), 1.0);
        v = (float)(1.0 - c);
    }
    for (int o = 16; o > 0; o >>= 1) v += __shfl_down_sync(0xffffffffu, v, o);
    if (t == 0) out[0] = v / (float)NIMG;
}

// ---------------------------------------------------------------------------
extern "C" void kernel_launch(void* const* d_in, const int* in_sizes, int n_in,
                              void* d_out, int out_size)
{
    const float* logits = (const float*)d_in[0];
    const int*   target = (const int*)d_in[1];
    float*       out    = (float*)d_out;

    float *A = nullptr, *B = nullptr;
    cudaGetSymbolAddress((void**)&A, g_bufA);
    cudaGetSymbolAddress((void**)&B, g_bufB);

    dim3 grid(XT, IMG_H / (R * NWARP), NF);   // 9 x 8 x 32 = 2304 blocks
    const int blk = NWARP * 32;

    skel_kernel<0><<<grid, blk>>>(nullptr, logits, target, A);  // sigmoid + iters 1-2
    skel_kernel<1><<<grid, blk>>>(A, nullptr, nullptr, B);      // iters 3-4
    skel_kernel<2><<<grid, blk>>>(B, logits, target, nullptr);  // iter 5 + reduce
    final_kernel<<<1, 32>>>(out);
}

// round 10
// speedup vs baseline: 1.9610x; 1.4156x over previous
#include <cuda_runtime.h>
#include <cuda_fp16.h>
#include <math_constants.h>

#define IMG_H 1024
#define IMG_W 1024
#define IMG   (IMG_H * IMG_W)
#define NIMG  16
#define NF    32            // [0..15]=pred(sigmoid(logits)), [16..31]=gt(target)
#define OUTC  240           // emitted cols per warp (256-col window, lanes 0/31 halo)
#define XT    5             // ceil(1024/240)
#define R     32            // emitted rows per warp
#define NWARP 4

__device__ __half  g_bufA[(size_t)NF * IMG];   // 64 MB scratch
__device__ __half  g_bufB[(size_t)NF * IMG];   // 64 MB scratch
__device__ double  g_acc[NF];                  // [0..15]=tp, [16..31]=ts

struct __align__(16) h8 { __half2 a, b, c, d; };   // 8 cols per lane

__device__ __forceinline__ float sigmoidf(float x) { return 1.f / (1.f + __expf(-x)); }
__device__ __forceinline__ unsigned h2u(__half2 v) { return *(unsigned*)&v; }
__device__ __forceinline__ __half2  u2h(unsigned u) { return *(__half2*)&u; }
// pair (hi of x, lo of y)
__device__ __forceinline__ __half2 pmh(__half2 x, __half2 y) {
    return u2h(__byte_perm(h2u(x), h2u(y), 0x5432));
}
__device__ __forceinline__ h8 vmin38(h8 x, h8 y, h8 z) {
    h8 o;
    o.a = __hmin2(x.a, __hmin2(y.a, z.a));
    o.b = __hmin2(x.b, __hmin2(y.b, z.b));
    o.c = __hmin2(x.c, __hmin2(y.c, z.c));
    o.d = __hmin2(x.d, __hmin2(y.d, z.d));
    return o;
}
__device__ __forceinline__ h8 vmax38(h8 x, h8 y, h8 z) {
    h8 o;
    o.a = __hmax2(x.a, __hmax2(y.a, z.a));
    o.b = __hmax2(x.b, __hmax2(y.b, z.b));
    o.c = __hmax2(x.c, __hmax2(y.c, z.c));
    o.d = __hmax2(x.d, __hmax2(y.d, z.d));
    return o;
}
__device__ __forceinline__ h8 hmin8(h8 v) {
    __half2 L  = u2h(__shfl_up_sync(0xffffffffu, h2u(v.d), 1));
    __half2 Rt = u2h(__shfl_down_sync(0xffffffffu, h2u(v.a), 1));
    __half2 p0 = pmh(L,   v.a), p1 = pmh(v.a, v.b), p2 = pmh(v.b, v.c);
    __half2 p3 = pmh(v.c, v.d), p4 = pmh(v.d, Rt);
    h8 o;
    o.a = __hmin2(p0, __hmin2(v.a, p1));
    o.b = __hmin2(p1, __hmin2(v.b, p2));
    o.c = __hmin2(p2, __hmin2(v.c, p3));
    o.d = __hmin2(p3, __hmin2(v.d, p4));
    return o;
}
__device__ __forceinline__ h8 hmax8(h8 v) {
    __half2 L  = u2h(__shfl_up_sync(0xffffffffu, h2u(v.d), 1));
    __half2 Rt = u2h(__shfl_down_sync(0xffffffffu, h2u(v.a), 1));
    __half2 p0 = pmh(L,   v.a), p1 = pmh(v.a, v.b), p2 = pmh(v.b, v.c);
    __half2 p3 = pmh(v.c, v.d), p4 = pmh(v.d, Rt);
    h8 o;
    o.a = __hmax2(p0, __hmax2(v.a, p1));
    o.b = __hmax2(p1, __hmax2(v.b, p2));
    o.c = __hmax2(p2, __hmax2(v.c, p3));
    o.d = __hmax2(p3, __hmax2(v.d, p4));
    return o;
}
// clamp01(x - (op - er))
__device__ __forceinline__ h8 upd8(h8 x, h8 op, h8 er) {
    const __half2 Z = __float2half2_rn(0.f), O = __float2half2_rn(1.f);
    h8 o;
    o.a = __hmin2(__hmax2(__hsub2(x.a, __hsub2(op.a, er.a)), Z), O);
    o.b = __hmin2(__hmax2(__hsub2(x.b, __hsub2(op.b, er.b)), Z), O);
    o.c = __hmin2(__hmax2(__hsub2(x.c, __hsub2(op.c, er.c)), Z), O);
    o.d = __hmin2(__hmax2(__hsub2(x.d, __hsub2(op.d, er.d)), Z), O);
    return o;
}
// lane-uniform column masks
__device__ __forceinline__ h8 maskN8(h8 e, __half2 m) {   // invalid lane -> -inf
    h8 o; o.a = __hmin2(e.a, m); o.b = __hmin2(e.b, m);
    o.c = __hmin2(e.c, m); o.d = __hmin2(e.d, m); return o;
}
__device__ __forceinline__ h8 maskP8(h8 e, __half2 m) {   // invalid lane -> +inf
    h8 o; o.a = __hmax2(e.a, m); o.b = __hmax2(e.b, m);
    o.c = __hmax2(e.c, m); o.d = __hmax2(e.d, m); return o;
}

// ---------------------------------------------------------------------------
// MODE 0: x = sigmoid(logits)/(float)target; 2 skeleton iterations; store half.
// MODE 1: load half buffer; 2 skeleton iterations; store half.
// MODE 2: load half buffer; 1 skeleton iteration; accumulate tp/ts.
// Lane owns 8 cols (4x half2, one uint4 per row). Window 256 cols, emit 240.
// Column validity is lane-uniform (no straddling). Lanes 0/31 are halo.
// ---------------------------------------------------------------------------
template<int MODE>
__global__ void __launch_bounds__(NWARP * 32)
skel_kernel(const __half* __restrict__ src,
            const float*  __restrict__ logits,
            const int*    __restrict__ target,
            __half*       __restrict__ dst)
{
    const int lane = threadIdx.x & 31;
    const int warp = threadIdx.x >> 5;
    const int z    = blockIdx.z;
    const int c0   = blockIdx.x * OUTC - 8 + lane * 8;   // multiple of 8
    const int row0 = (blockIdx.y * NWARP + warp) * R;
    const bool colsOK = (c0 >= 0) && (c0 < IMG_W);       // whole-lane validity

    if (MODE == 0 && blockIdx.x == 0 && blockIdx.y == 0 && blockIdx.z == 0 &&
        threadIdx.x < NF)
        g_acc[threadIdx.x] = 0.0;   // stream-ordered before MODE 2 atomics

    const int img = (z < NIMG) ? z : z - NIMG;
    const float* __restrict__ lg = logits + (size_t)img * IMG;
    const int*   __restrict__ tg = target + (size_t)img * IMG;
    const __half* __restrict__ sp = (MODE != 0) ? src + (size_t)z * IMG : nullptr;
    __half* __restrict__ dp = (MODE != 2) ? dst + (size_t)z * IMG : nullptr;

    const __half hinf  = __ushort_as_half(0x7C00);
    const __half hninf = __ushort_as_half(0xFC00);
    const __half2 INF2 = __half2half2(hinf), NINF2 = __half2half2(hninf);
    h8 P8; P8.a = INF2;  P8.b = INF2;  P8.c = INF2;  P8.d = INF2;
    h8 N8; N8.a = NINF2; N8.b = NINF2; N8.c = NINF2; N8.d = NINF2;
    const __half2 mN2 = colsOK ? INF2 : NINF2;   // apply with hmin2
    const __half2 mP2 = colsOK ? NINF2 : INF2;   // apply with hmax2

    const bool emitLane = (lane >= 1) && (lane <= 30) && colsOK;

    auto ldF = [&](int r) -> h8 {               // no checks (interior)
        size_t off = (size_t)r * IMG_W + c0;
        if (MODE == 0) {
            h8 o;
            if (z < NIMG) {
                float4 f1 = __ldg((const float4*)(lg + off));
                float4 f2 = __ldg((const float4*)(lg + off + 4));
                o.a = __floats2half2_rn(sigmoidf(f1.x), sigmoidf(f1.y));
                o.b = __floats2half2_rn(sigmoidf(f1.z), sigmoidf(f1.w));
                o.c = __floats2half2_rn(sigmoidf(f2.x), sigmoidf(f2.y));
                o.d = __floats2half2_rn(sigmoidf(f2.z), sigmoidf(f2.w));
            } else {
                int4 t1 = __ldg((const int4*)(tg + off));
                int4 t2 = __ldg((const int4*)(tg + off + 4));
                o.a = __floats2half2_rn((float)t1.x, (float)t1.y);
                o.b = __floats2half2_rn((float)t1.z, (float)t1.w);
                o.c = __floats2half2_rn((float)t2.x, (float)t2.y);
                o.d = __floats2half2_rn((float)t2.z, (float)t2.w);
            }
            return o;
        }
        uint4 u = __ldg((const uint4*)(sp + off));
        h8 o; o.a = u2h(u.x); o.b = u2h(u.y); o.c = u2h(u.z); o.d = u2h(u.w);
        return o;
    };
    auto ldrow = [&](int r) -> h8 {             // checked (edges)
        if (!colsOK || (unsigned)r >= IMG_H) return P8;
        return ldF(r);
    };
    auto store8 = [&](int r, h8 v) {
        uint4 u; u.x = h2u(v.a); u.y = h2u(v.b); u.z = h2u(v.c); u.w = h2u(v.d);
        *(uint4*)(dp + (size_t)r * IMG_W + c0) = u;
    };

    const bool cint = (blockIdx.x > 0) && (blockIdx.x < gridDim.x - 1);
    const bool rint = (row0 >= 4) && (row0 + R + 4 <= IMG_H);
    float accum = 0.f;

    if (MODE != 2) {
        if (cint && rint) {
            // ---- FAST: two fused iterations, no checks ----
            h8 xa = ldF(row0 - 4), xb = ldF(row0 - 3);
            h8 e1a = N8, e1b = N8, pa = P8, pb = P8, qa = N8, qb = N8;
            #pragma unroll 2
            for (int k = row0 - 3; k <= row0 + R + 2; ++k) {
                h8 xc  = ldF(k + 1);
                h8 e1  = hmin8(vmin38(xa, xb, xc));
                h8 op1 = hmax8(vmax38(e1a, e1b, e1));
                h8 xp  = upd8(xa, op1, e1b);
                h8 e2  = hmin8(vmin38(pa, pb, xp));
                if (k >= row0 + 3) {
                    h8 op2 = hmax8(vmax38(qa, qb, e2));
                    h8 nx  = upd8(pa, op2, qb);
                    if (emitLane) store8(k - 3, nx);
                }
                qa = qb; qb = e2; pa = pb; pb = xp;
                e1a = e1b; e1b = e1; xa = xb; xb = xc;
            }
        } else {
            // ---- CHECKED: row selects + lane-uniform column masks ----
            h8 xa = ldrow(row0 - 4), xb = ldrow(row0 - 3);
            h8 e1a = N8, e1b = N8, pa = P8, pb = P8, qa = N8, qb = N8;
            for (int k = row0 - 3; k <= row0 + R + 2; ++k) {
                h8 xc = ldrow(k + 1);
                h8 e1 = ((unsigned)k < IMG_H)
                      ? maskN8(hmin8(vmin38(xa, xb, xc)), mN2) : N8;
                h8 op1 = hmax8(vmax38(e1a, e1b, e1));
                h8 xp  = ((unsigned)(k - 1) < IMG_H)
                       ? maskP8(upd8(xa, op1, e1b), mP2) : P8;
                h8 e2 = ((unsigned)(k - 2) < IMG_H)
                      ? maskN8(hmin8(vmin38(pa, pb, xp)), mN2) : N8;
                if (k >= row0 + 3) {
                    h8 op2 = hmax8(vmax38(qa, qb, e2));
                    h8 nx  = upd8(pa, op2, qb);
                    if (emitLane) store8(k - 3, nx);
                }
                qa = qb; qb = e2; pa = pb; pb = xp;
                e1a = e1b; e1b = e1; xa = xb; xb = xc;
            }
        }
    } else {
        // ---- final iteration + reduction ----
        auto weight8 = [&](size_t ob, float* w) {
            if (z < NIMG) {
                int4 t1 = __ldg((const int4*)(tg + ob));
                int4 t2 = __ldg((const int4*)(tg + ob + 4));
                w[0]=(float)t1.x; w[1]=(float)t1.y; w[2]=(float)t1.z; w[3]=(float)t1.w;
                w[4]=(float)t2.x; w[5]=(float)t2.y; w[6]=(float)t2.z; w[7]=(float)t2.w;
            } else {
                float4 f1 = __ldg((const float4*)(lg + ob));
                float4 f2 = __ldg((const float4*)(lg + ob + 4));
                w[0]=sigmoidf(f1.x); w[1]=sigmoidf(f1.y); w[2]=sigmoidf(f1.z); w[3]=sigmoidf(f1.w);
                w[4]=sigmoidf(f2.x); w[5]=sigmoidf(f2.y); w[6]=sigmoidf(f2.z); w[7]=sigmoidf(f2.w);
            }
        };
        auto accum8 = [&](int r, h8 nx) {
            size_t ob = (size_t)r * IMG_W + c0;
            float w[8]; weight8(ob, w);
            float2 f0 = __half22float2(nx.a), f1 = __half22float2(nx.b);
            float2 f2 = __half22float2(nx.c), f3 = __half22float2(nx.d);
            accum += f0.x * w[0] + f0.y * w[1] + f1.x * w[2] + f1.y * w[3]
                   + f2.x * w[4] + f2.y * w[5] + f3.x * w[6] + f3.y * w[7];
        };
        if (cint && rint) {
            h8 xa = ldF(row0 - 2), xb = ldF(row0 - 1);
            h8 e1a = N8, e1b = N8;
            #pragma unroll 2
            for (int k = row0 - 1; k <= row0 + R; ++k) {
                h8 xc = ldF(k + 1);
                h8 e1 = hmin8(vmin38(xa, xb, xc));
                if (k >= row0 + 1) {
                    h8 op = hmax8(vmax38(e1a, e1b, e1));
                    h8 nx = upd8(xa, op, e1b);
                    if (emitLane) accum8(k - 1, nx);
                }
                e1a = e1b; e1b = e1; xa = xb; xb = xc;
            }
        } else {
            h8 xa = ldrow(row0 - 2), xb = ldrow(row0 - 1);
            h8 e1a = N8, e1b = N8;
            for (int k = row0 - 1; k <= row0 + R; ++k) {
                h8 xc = ldrow(k + 1);
                h8 e1 = ((unsigned)k < IMG_H)
                      ? maskN8(hmin8(vmin38(xa, xb, xc)), mN2) : N8;
                if (k >= row0 + 1) {
                    h8 op = hmax8(vmax38(e1a, e1b, e1));
                    h8 nx = upd8(xa, op, e1b);
                    if (emitLane) accum8(k - 1, nx);
                }
                e1a = e1b; e1b = e1; xa = xb; xb = xc;
            }
        }
        #pragma unroll
        for (int o = 16; o > 0; o >>= 1)
            accum += __shfl_down_sync(0xffffffffu, accum, o);
        __shared__ float sacc[NWARP];
        if (lane == 0) sacc[warp] = accum;
        __syncthreads();
        if (threadIdx.x == 0) {
            float t = 0.f;
            #pragma unroll
            for (int i = 0; i < NWARP; ++i) t += sacc[i];
            atomicAdd(&g_acc[z], (double)t);
        }
    }
}

// ---------------------------------------------------------------------------
__global__ void final_kernel(float* __restrict__ out)
{
    const int t = threadIdx.x;
    float v = 0.f;
    if (t < NIMG) {
        double tp = g_acc[t], ts = g_acc[NIMG + t];
        double num = 2.0 * tp * ts;
        double den = tp + ts;
        double c = (den > 0.0) ? (num + 1e-6) / (den + 1e-6) : 1.0;
        c = fmin(fmax(c, 0.0), 1.0);
        v = (float)(1.0 - c);
    }
    for (int o = 16; o > 0; o >>= 1) v += __shfl_down_sync(0xffffffffu, v, o);
    if (t == 0) out[0] = v / (float)NIMG;
}

// ---------------------------------------------------------------------------
extern "C" void kernel_launch(void* const* d_in, const int* in_sizes, int n_in,
                              void* d_out, int out_size)
{
    const float* logits = (const float*)d_in[0];
    const int*   target = (const int*)d_in[1];
    float*       out    = (float*)d_out;

    __half *A = nullptr, *B = nullptr;
    cudaGetSymbolAddress((void**)&A, g_bufA);
    cudaGetSymbolAddress((void**)&B, g_bufB);

    dim3 grid(XT, IMG_H / (R * NWARP), NF);   // 5 x 8 x 32 = 1280 blocks
    const int blk = NWARP * 32;

    skel_kernel<0><<<grid, blk>>>(nullptr, logits, target, A);  // sigmoid + iters 1-2
    skel_kernel<1><<<grid, blk>>>(A, nullptr, nullptr, B);      // iters 3-4
    skel_kernel<2><<<grid, blk>>>(B, logits, target, nullptr);  // iter 5 + reduce
    final_kernel<<<1, 32>>>(out);
}